// round 15
// baseline (speedup 1.0000x reference)
#include <cuda_runtime.h>
#include <cuda_fp16.h>
#include <cstdint>

namespace {

constexpr int Bn = 2, Tn = 2111, Qn = 2048, Cn = 64, Hn = 8, DMn = 512;

// Scratch (device globals) — plain fp16 pipeline
__device__ __half g_projh[(size_t)Bn * Tn * 1536];  // [k|v|hq] fp16
__device__ __half g_hrh[Cn * 512];
__device__ float g_bias[1536];
__device__ unsigned char g_mask[Bn * (Cn - 1)];
__device__ __half g_xh[(size_t)Bn * Tn * 512];
__device__ __half g_atth[(size_t)Bn * Qn * 512];
__device__ __half g_Wh[512 * 1536];                 // [Wkv | Wq]
__device__ __half g_Woh[512 * 512];                 // Wo

// ===========================================================================
// PTX helpers
// ===========================================================================
__device__ __forceinline__ uint32_t smem_u32(const void* p) {
    uint32_t a;
    asm("{ .reg .u64 t; cvta.to.shared.u64 t, %1; cvt.u32.u64 %0, t; }" : "=r"(a) : "l"(p));
    return a;
}
__device__ __forceinline__ void cpa16(uint32_t d, const void* s, int sz) {
    asm volatile("cp.async.cg.shared.global [%0], [%1], 16, %2;" :: "r"(d), "l"(s), "r"(sz));
}
__device__ __forceinline__ void cp_commit() { asm volatile("cp.async.commit_group;"); }
template <int N> __device__ __forceinline__ void cp_wait() {
    asm volatile("cp.async.wait_group %0;" :: "n"(N));
}
__device__ __forceinline__ void ldsm4(uint32_t* r, uint32_t a) {
    asm volatile("ldmatrix.sync.aligned.m8n8.x4.shared.b16 {%0,%1,%2,%3}, [%4];"
                 : "=r"(r[0]), "=r"(r[1]), "=r"(r[2]), "=r"(r[3]) : "r"(a));
}
__device__ __forceinline__ void ldsm4t(uint32_t* r, uint32_t a) {
    asm volatile("ldmatrix.sync.aligned.m8n8.x4.trans.shared.b16 {%0,%1,%2,%3}, [%4];"
                 : "=r"(r[0]), "=r"(r[1]), "=r"(r[2]), "=r"(r[3]) : "r"(a));
}
__device__ __forceinline__ void mma_f32(float* d, const uint32_t* a, uint32_t b0, uint32_t b1) {
    asm volatile(
        "mma.sync.aligned.m16n8k16.row.col.f32.f16.f16.f32 "
        "{%0,%1,%2,%3}, {%4,%5,%6,%7}, {%8,%9}, {%0,%1,%2,%3};"
        : "+f"(d[0]), "+f"(d[1]), "+f"(d[2]), "+f"(d[3])
        : "r"(a[0]), "r"(a[1]), "r"(a[2]), "r"(a[3]), "r"(b0), "r"(b1));
}
__device__ __forceinline__ void mma_f16(uint32_t* d, const uint32_t* a, uint32_t b0, uint32_t b1) {
    asm volatile(
        "mma.sync.aligned.m16n8k16.row.col.f16.f16.f16.f16 "
        "{%0,%1}, {%2,%3,%4,%5}, {%6,%7}, {%0,%1};"
        : "+r"(d[0]), "+r"(d[1])
        : "r"(a[0]), "r"(a[1]), "r"(a[2]), "r"(a[3]), "r"(b0), "r"(b1));
}

// ===========================================================================
// HGEMM, 128x64 tile, 2 CTAs/SM.
//  PROJ=true (A=g_xh): v cols [512,1024) f32acc; k/hq cols f16acc (scores
//    only -> softmax attenuates). v-first column remap (heavy CTAs first).
//    fp16 out (+bias).
//  PROJ=false (Wo, A=g_atth): f32acc, fp32 out.
// ===========================================================================
constexpr int OFF_AH = 0;          // 128 rows x 64B
constexpr int OFF_BH = 8192;       // 32 rows x 128B
constexpr int STG = 12288;
constexpr int NSTAGE = 4;
constexpr int HG_SMEM = STG * NSTAGE;  // 49152

template <bool PROJ>
__global__ __launch_bounds__(256, 2) void hgemm_kernel(
    const __half* __restrict__ A, const __half* __restrict__ Bw,
    const float* __restrict__ bias, float* __restrict__ Cf,
    __half* __restrict__ Ch, int M, int N)
{
    extern __shared__ char smm[];
    uint32_t sb = smem_u32(smm);
    int tid = threadIdx.x, lane = tid & 31, wid = tid >> 5;
    int wm = wid >> 1, wn = wid & 1;
    int colIdx = PROJ ? (int)((blockIdx.x + 8) % 24) : (int)blockIdx.x;
    int row0 = blockIdx.y * 128, col0 = colIdx * 64;

    const bool use_f32 = (!PROJ) || (col0 >= 512 && col0 < 1024);

    int idA0 = tid, idA1 = tid + 256;
    int rA0 = idA0 >> 2, cA0 = idA0 & 3;
    int rA1 = idA1 >> 2, cA1 = idA1 & 3;
    int gm0 = row0 + rA0, gm1 = row0 + rA1;
    int av0 = (gm0 < M) ? 16 : 0, av1 = (gm1 < M) ? 16 : 0;
    size_t arow0 = (gm0 < M) ? (size_t)gm0 : 0;
    size_t arow1 = (gm1 < M) ? (size_t)gm1 : 0;
    const __half* asrc0 = A + arow0 * 512 + cA0 * 8;
    const __half* asrc1 = A + arow1 * 512 + cA1 * 8;
    uint32_t adst0 = rA0 * 64 + (((cA0 + (rA0 >> 1)) & 3) << 4);
    uint32_t adst1 = rA1 * 64 + (((cA1 + (rA1 >> 1)) & 3) << 4);

    int rB = tid >> 3, cB = tid & 7;
    const __half* bsrc = Bw + (size_t)rB * N + col0 + cB * 8;
    uint32_t bdst = rB * 128 + ((cB ^ (rB & 7)) << 4);

    auto load_stage = [&](int s, int kt) {
        int k0 = kt * 32;
        uint32_t base = sb + s * STG;
        cpa16(base + OFF_AH + adst0, asrc0 + k0, av0);
        cpa16(base + OFF_AH + adst1, asrc1 + k0, av1);
        cpa16(base + OFF_BH + bdst, bsrc + (size_t)k0 * N, 16);
        cp_commit();
    };

    constexpr int KT = 512 / 32;   // 16
    load_stage(0, 0);
    load_stage(1, 1);
    load_stage(2, 2);

    float accf[2][4][4] = {};
    uint32_t acch[2][4][2] = {};

    int la_r0 = wm * 32 + (lane & 15);
    int la_c0 = (lane >> 4);
    int lb_r0 = (lane & 15);
    int lb_c0 = wn * 4 + (lane >> 4);

    for (int kt = 0; kt < KT; kt++) {
        cp_wait<2>();
        __syncthreads();
        int s = kt & (NSTAGE - 1);
        uint32_t base = sb + s * STG;
#pragma unroll
        for (int kk = 0; kk < 2; kk++) {
            uint32_t ah[2][4];
#pragma unroll
            for (int mf = 0; mf < 2; mf++) {
                int r = la_r0 + mf * 16;
                int c = la_c0 + kk * 2;
                ldsm4(ah[mf], base + OFF_AH + r * 64 + (((c + (r >> 1)) & 3) << 4));
            }
            uint32_t bh[2][4];
#pragma unroll
            for (int nf = 0; nf < 2; nf++) {
                int r = lb_r0 + kk * 16;
                int c = lb_c0 + nf * 2;
                ldsm4t(bh[nf], base + OFF_BH + r * 128 + ((c ^ (r & 7)) << 4));
            }
#pragma unroll
            for (int mf = 0; mf < 2; mf++)
#pragma unroll
                for (int n = 0; n < 4; n++) {
                    int bi = n >> 1, br = (n & 1) * 2;
                    if (use_f32)
                        mma_f32(accf[mf][n], ah[mf], bh[bi][br], bh[bi][br + 1]);
                    else
                        mma_f16(acch[mf][n], ah[mf], bh[bi][br], bh[bi][br + 1]);
                }
        }
        if (kt + 3 < KT) load_stage((kt + 3) & (NSTAGE - 1), kt + 3);
        else cp_commit();
    }

    // ---- epilogue ----
#pragma unroll
    for (int mf = 0; mf < 2; mf++) {
        int rb = row0 + wm * 32 + mf * 16 + (lane >> 2);
#pragma unroll
        for (int n = 0; n < 4; n++) {
            int cb = col0 + wn * 32 + n * 8 + (lane & 3) * 2;
            float* a4 = accf[mf][n];
            float2 lo2 = __half22float2(*(__half2*)&acch[mf][n][0]);
            float2 hi2 = __half22float2(*(__half2*)&acch[mf][n][1]);
            float bx = 0.f, by = 0.f;
            if (PROJ) { bx = bias[cb]; by = bias[cb + 1]; }
            float v00, v01, v10, v11;
            if (use_f32) {
                v00 = a4[0] + bx; v01 = a4[1] + by;
                v10 = a4[2] + bx; v11 = a4[3] + by;
            } else {
                v00 = lo2.x + bx; v01 = lo2.y + by;
                v10 = hi2.x + bx; v11 = hi2.y + by;
            }
            if (PROJ) {
                if (rb < M)
                    *(__half2*)(Ch + (size_t)rb * 1536 + cb) = __floats2half2_rn(v00, v01);
                if (rb + 8 < M)
                    *(__half2*)(Ch + (size_t)(rb + 8) * 1536 + cb) = __floats2half2_rn(v10, v11);
            } else {
                if (rb < M)
                    *(float2*)(Cf + (size_t)rb * N + cb) = make_float2(v00, v01);
                if (rb + 8 < M)
                    *(float2*)(Cf + (size_t)(rb + 8) * N + cb) = make_float2(v10, v11);
            }
        }
    }
}

// ===========================================================================
// prep kernel: convX + convW2 + convWo + mask + hr(32 blocks) in one launch.
// ===========================================================================
constexpr int PREP_BLOCKS = 3293;

__global__ __launch_bounds__(256) void prep_kernel(
    const float* __restrict__ x, const float* __restrict__ r,
    const float* __restrict__ Wkv, const float* __restrict__ Wq,
    const float* __restrict__ bq, const float* __restrict__ Wr,
    const float* __restrict__ Wo)
{
    int bid = blockIdx.x, tid = threadIdx.x;
    if (bid < 2111) {
        int idx = bid * 256 + tid;
        int m = idx >> 7, k4 = (idx & 127) << 2;
        float4 v = *(const float4*)(x + (size_t)m * 512 + k4);
        __half* rb = g_xh + (size_t)m * 512;
        *(__half2*)(rb + k4) = __floats2half2_rn(v.x, v.y);
        *(__half2*)(rb + k4 + 2) = __floats2half2_rn(v.z, v.w);
    } else if (bid < 2879) {
        int idx = (bid - 2111) * 256 + tid;
        if (idx < 384) {
            float4 v = make_float4(0.f, 0.f, 0.f, 0.f);
            int n4 = idx * 4;
            if (n4 >= 1024) v = *(const float4*)(bq + n4 - 1024);
            *(float4*)(g_bias + n4) = v;
        }
        int k = idx / 384, n4 = (idx - k * 384) * 4;
        float4 v = (n4 < 1024) ? *(const float4*)(Wkv + (size_t)k * 1024 + n4)
                               : *(const float4*)(Wq + (size_t)k * 512 + n4 - 1024);
        __half* d0 = g_Wh + (size_t)k * 1536 + n4;
        *(__half2*)(d0) = __floats2half2_rn(v.x, v.y);
        *(__half2*)(d0 + 2) = __floats2half2_rn(v.z, v.w);
    } else if (bid < 3135) {
        int idx = (bid - 2879) * 256 + tid;
        int k = idx >> 7, n4 = (idx & 127) << 2;
        float4 v = *(const float4*)(Wo + (size_t)k * 512 + n4);
        __half* d0 = g_Woh + (size_t)k * 512 + n4;
        *(__half2*)(d0) = __floats2half2_rn(v.x, v.y);
        *(__half2*)(d0 + 2) = __floats2half2_rn(v.z, v.w);
    } else if (bid < 3261) {
        int mb = bid - 3135;
        int t = mb % (Cn - 1), b = mb / (Cn - 1);
        const float* row = x + ((size_t)b * Tn + t) * DMn;
        int zero = 1;
        for (int i = tid; i < DMn; i += 256)
            if (row[i] != 0.f) zero = 0;
        int all = __syncthreads_and(zero);
        if (tid == 0) g_mask[b * (Cn - 1) + t] = (unsigned char)(all != 0);
    } else {
        // hr: block cb computes hr[:, cb*16 : cb*16+16] = r @ Wr slice
        __shared__ float sa[64][33];
        __shared__ float sw[32][16];
        int cb = bid - 3261;
        int row = tid & 63, cg = tid >> 6;   // cg 0..3 -> 4 cols each
        float acc[4] = {};
        for (int k0 = 0; k0 < 512; k0 += 32) {
            for (int i = tid; i < 2048; i += 256) {
                int rr = i >> 5, kk = i & 31;
                sa[rr][kk] = r[rr * 512 + k0 + kk];
            }
            for (int i = tid; i < 512; i += 256) {   // FIX: cover all 512 elems
                int kk = i >> 4, cc = i & 15;
                sw[kk][cc] = Wr[(size_t)(k0 + kk) * 512 + cb * 16 + cc];
            }
            __syncthreads();
#pragma unroll 8
            for (int kk = 0; kk < 32; kk++) {
                float a = sa[row][kk];
#pragma unroll
                for (int c = 0; c < 4; c++)
                    acc[c] = fmaf(a, sw[kk][cg * 4 + c], acc[c]);
            }
            __syncthreads();
        }
        __half* dst = g_hrh + row * 512 + cb * 16 + cg * 4;
        *(__half2*)(dst) = __floats2half2_rn(acc[0], acc[1]);
        *(__half2*)(dst + 2) = __floats2half2_rn(acc[2], acc[3]);
    }
}

// ---------------------------------------------------------------------------
// Tensor-core attention, 3 CTAs/SM, plain fp16 V. Output: fp16.
// ---------------------------------------------------------------------------
constexpr int AS_V  = 0;
constexpr int AS_DYN = 9216;
constexpr int AS_TOTAL = AS_DYN + 17408;          // 26624 halves
constexpr int ATT_SMEM = AS_TOTAL * 2;            // 53248 B

__global__ __launch_bounds__(256, 3) void attn_kernel() {
    extern __shared__ __align__(16) __half sm[];
    __half* sV  = sm + AS_V;
    __half* sHq = sm + AS_DYN;
    __half* sKC = sm + AS_DYN + 4608;
    __half* sS  = sm + AS_DYN;            // overlays sHq/sKC after score MMA
    __half* sW  = sm + AS_DYN + 8320;

    int q0 = blockIdx.x * 64;
    int h = blockIdx.y, b = blockIdx.z;
    int tid = threadIdx.x, lane = tid & 31, wid = tid >> 5;
    int wm = wid >> 1, wn = wid & 1;

    const __half* pb = g_projh + (size_t)(b * Tn + q0) * 1536;

    for (int li = tid; li < 1024; li += 256) {
        int q = li >> 4, d4 = (li & 15) << 2;
        *(uint2*)(sHq + q * 72 + d4) =
            *(const uint2*)(pb + (size_t)(63 + q) * 1536 + 1024 + h * 64 + d4);
    }
    for (int li = tid; li < 2048; li += 256) {
        int j = li >> 4, d4 = (li & 15) << 2;
        __half hv[4];
        if (j < 127) *(uint2*)hv = *(const uint2*)(pb + (size_t)j * 1536 + h * 64 + d4);
        else { hv[0] = hv[1] = hv[2] = hv[3] = __half(0.f); }
        sKC[(d4 + 0) * 200 + j] = hv[0];
        sKC[(d4 + 1) * 200 + j] = hv[1];
        sKC[(d4 + 2) * 200 + j] = hv[2];
        sKC[(d4 + 3) * 200 + j] = hv[3];
    }
    for (int li = tid; li < 1024; li += 256) {
        int c = li >> 4, d4 = (li & 15) << 2;
        __half hv[4];
        *(uint2*)hv = *(const uint2*)(g_hrh + c * 512 + h * 64 + d4);
        sKC[(d4 + 0) * 200 + 128 + c] = hv[0];
        sKC[(d4 + 1) * 200 + 128 + c] = hv[1];
        sKC[(d4 + 2) * 200 + 128 + c] = hv[2];
        sKC[(d4 + 3) * 200 + 128 + c] = hv[3];
    }
    for (int li = tid; li < 2048; li += 256) {
        int j = li >> 4, d4 = (li & 15) << 2;
        uint2 hv = make_uint2(0, 0);
        if (j < 127) hv = *(const uint2*)(pb + (size_t)j * 1536 + 512 + h * 64 + d4);
        *(uint2*)(sV + j * 72 + d4) = hv;
    }
    __syncthreads();

    uint32_t uHq = smem_u32(sHq), uKC = smem_u32(sKC);
    float sacc[6][2][4] = {};
#pragma unroll
    for (int ks = 0; ks < 4; ks++) {
        uint32_t a[4];
        {
            int r = wm * 16 + (lane & 15);
            int c = (lane >> 4) + ks * 2;
            ldsm4(a, uHq + r * 144 + c * 16);
        }
#pragma unroll
        for (int nf = 0; nf < 6; nf++) {
            uint32_t bb[4];
            int r = (lane & 15) + ks * 16;
            int c = wn * 12 + nf * 2 + (lane >> 4);
            ldsm4t(bb, uKC + r * 400 + c * 16);
            mma_f32(sacc[nf][0], a, bb[0], bb[1]);
            mma_f32(sacc[nf][1], a, bb[2], bb[3]);
        }
    }
    __syncthreads();

    for (int i = tid; i < 64 * 136 / 2; i += 256) ((uint32_t*)sW)[i] = 0;
    {
        int row = wm * 16 + (lane >> 2);
        auto put = [&](int rr, int cc, float v) {
            int rel = cc - rr;
            if (rel >= 0 && rel < 64) sS[rr * 130 + rel] = __float2half_rn(v);
            else if (cc >= 128) sS[rr * 130 + 64 + (cc - 128)] = __float2half_rn(v);
        };
#pragma unroll
        for (int nf = 0; nf < 6; nf++)
#pragma unroll
            for (int sub = 0; sub < 2; sub++) {
                int col = wn * 96 + nf * 16 + sub * 8 + (lane & 3) * 2;
                float* c4 = sacc[nf][sub];
                put(row, col, c4[0]);     put(row, col + 1, c4[1]);
                put(row + 8, col, c4[2]); put(row + 8, col + 1, c4[3]);
            }
    }
    __syncthreads();

    {
        int w = tid >> 5;
#pragma unroll
        for (int rr = 0; rr < 8; rr++) {
            int q = w * 8 + rr;
            int c0 = lane, c1 = lane + 32;
            float s0 = (__half2float(sS[q * 130 + c0]) +
                        __half2float(sS[q * 130 + 64 + c0])) * 0.125f;
            float s1 = (__half2float(sS[q * 130 + c1]) +
                        __half2float(sS[q * 130 + 64 + c1])) * 0.125f;
            int jg0 = q0 + q + c0, jg1 = q0 + q + c1;
            if (jg0 < Cn - 1 && g_mask[b * (Cn - 1) + jg0]) s0 = -1e30f;
            if (jg1 < Cn - 1 && g_mask[b * (Cn - 1) + jg1]) s1 = -1e30f;
            float mx = fmaxf(s0, s1);
#pragma unroll
            for (int o = 16; o; o >>= 1) mx = fmaxf(mx, __shfl_xor_sync(0xffffffffu, mx, o));
            float e0 = __expf(s0 - mx), e1 = __expf(s1 - mx);
            float sum = e0 + e1;
#pragma unroll
            for (int o = 16; o; o >>= 1) sum += __shfl_xor_sync(0xffffffffu, sum, o);
            float inv = 1.f / sum;
            sW[q * 136 + q + c0] = __float2half_rn(e0 * inv);
            sW[q * 136 + q + c1] = __float2half_rn(e1 * inv);
        }
    }
    __syncthreads();

    uint32_t uW = smem_u32(sW), uV = smem_u32(sV);
    {
        float ohi[4][4] = {};
#pragma unroll
        for (int ks = 0; ks < 8; ks++) {
            uint32_t a[4];
            {
                int r = wm * 16 + (lane & 15);
                int c = (lane >> 4) + ks * 2;
                ldsm4(a, uW + r * 272 + c * 16);
            }
#pragma unroll
            for (int nf = 0; nf < 2; nf++) {
                uint32_t bh[4];
                int r = (lane & 15) + ks * 16;
                int c = wn * 4 + nf * 2 + (lane >> 4);
                ldsm4t(bh, uV + r * 144 + c * 16);
                mma_f32(ohi[nf * 2], a, bh[0], bh[1]);
                mma_f32(ohi[nf * 2 + 1], a, bh[2], bh[3]);
            }
        }
        int row = wm * 16 + (lane >> 2);
#pragma unroll
        for (int n = 0; n < 4; n++) {
            int col = wn * 32 + n * 8 + (lane & 3) * 2;
#pragma unroll
            for (int rr = 0; rr < 2; rr++) {
                float ox = ohi[n][rr * 2], oy = ohi[n][rr * 2 + 1];
                int q = row + rr * 8;
                __half* dst = g_atth + (size_t)(b * Qn + q0 + q) * 512 + h * 64 + col;
                *(__half2*)(dst) = __floats2half2_rn(ox, oy);
            }
        }
    }
}

}  // namespace

// ---------------------------------------------------------------------------
extern "C" void kernel_launch(void* const* d_in, const int* in_sizes, int n_in,
                              void* d_out, int out_size) {
    const float* x   = (const float*)d_in[0];
    const float* r   = (const float*)d_in[1];
    const float* Wkv = (const float*)d_in[2];
    const float* Wq  = (const float*)d_in[3];
    const float* bq  = (const float*)d_in[4];
    const float* Wr  = (const float*)d_in[5];
    const float* Wo  = (const float*)d_in[6];
    float* out = (float*)d_out;

    float* biasp;
    __half *xh, *atth, *Wh, *Woh, *projh;
    cudaGetSymbolAddress((void**)&biasp, g_bias);
    cudaGetSymbolAddress((void**)&xh,    g_xh);
    cudaGetSymbolAddress((void**)&atth,  g_atth);
    cudaGetSymbolAddress((void**)&Wh,    g_Wh);
    cudaGetSymbolAddress((void**)&Woh,   g_Woh);
    cudaGetSymbolAddress((void**)&projh, g_projh);

    cudaFuncSetAttribute(attn_kernel, cudaFuncAttributeMaxDynamicSharedMemorySize, ATT_SMEM);
    cudaFuncSetAttribute(hgemm_kernel<true>,
                         cudaFuncAttributeMaxDynamicSharedMemorySize, HG_SMEM);
    cudaFuncSetAttribute(hgemm_kernel<false>,
                         cudaFuncAttributeMaxDynamicSharedMemorySize, HG_SMEM);

    // 1: prep (convX + convW2 + convWo + mask + hr)
    prep_kernel<<<PREP_BLOCKS, 256>>>(x, r, Wkv, Wq, bq, Wr, Wo);
    // 2: proj = x @ [Wkv|Wq] + [0|bq] -> fp16 (v f32acc first, k/hq f16acc)
    hgemm_kernel<true><<<dim3(24, 33), 256, HG_SMEM>>>(
        xh, Wh, biasp, nullptr, projh, Bn * Tn, 1536);
    // 3: tensor-core attention -> fp16 att
    attn_kernel<<<dim3(Qn / 64, Hn, Bn), 256, ATT_SMEM>>>();
    // 4: out = att @ Wo  (f32 acc, fp32 output)
    hgemm_kernel<false><<<dim3(8, 32), 256, HG_SMEM>>>(
        atth, Woh, nullptr, out, nullptr, Bn * Qn, 512);
}

// round 16
// speedup vs baseline: 1.0716x; 1.0716x over previous
#include <cuda_runtime.h>
#include <cuda_fp16.h>
#include <cstdint>

namespace {

constexpr int Bn = 2, Tn = 2111, Qn = 2048, Cn = 64, Hn = 8, DMn = 512;

// Scratch (device globals) — plain fp16 pipeline
__device__ __half g_projh[(size_t)Bn * Tn * 1536];  // [k|v|hq] fp16
__device__ __half g_hrh[Cn * 512];
__device__ float g_bias[1536];
__device__ unsigned char g_mask[Bn * (Cn - 1)];
__device__ __half g_xh[(size_t)Bn * Tn * 512];
__device__ __half g_atth[(size_t)Bn * Qn * 512];
__device__ __half g_Wh[512 * 1536];                 // [Wkv | Wq]
__device__ __half g_Woh[512 * 512];                 // Wo

// ===========================================================================
// PTX helpers
// ===========================================================================
__device__ __forceinline__ uint32_t smem_u32(const void* p) {
    uint32_t a;
    asm("{ .reg .u64 t; cvta.to.shared.u64 t, %1; cvt.u32.u64 %0, t; }" : "=r"(a) : "l"(p));
    return a;
}
__device__ __forceinline__ void cpa16(uint32_t d, const void* s, int sz) {
    asm volatile("cp.async.cg.shared.global [%0], [%1], 16, %2;" :: "r"(d), "l"(s), "r"(sz));
}
__device__ __forceinline__ void cp_commit() { asm volatile("cp.async.commit_group;"); }
template <int N> __device__ __forceinline__ void cp_wait() {
    asm volatile("cp.async.wait_group %0;" :: "n"(N));
}
__device__ __forceinline__ void ldsm4(uint32_t* r, uint32_t a) {
    asm volatile("ldmatrix.sync.aligned.m8n8.x4.shared.b16 {%0,%1,%2,%3}, [%4];"
                 : "=r"(r[0]), "=r"(r[1]), "=r"(r[2]), "=r"(r[3]) : "r"(a));
}
__device__ __forceinline__ void ldsm4t(uint32_t* r, uint32_t a) {
    asm volatile("ldmatrix.sync.aligned.m8n8.x4.trans.shared.b16 {%0,%1,%2,%3}, [%4];"
                 : "=r"(r[0]), "=r"(r[1]), "=r"(r[2]), "=r"(r[3]) : "r"(a));
}
__device__ __forceinline__ void mma_f32(float* d, const uint32_t* a, uint32_t b0, uint32_t b1) {
    asm volatile(
        "mma.sync.aligned.m16n8k16.row.col.f32.f16.f16.f32 "
        "{%0,%1,%2,%3}, {%4,%5,%6,%7}, {%8,%9}, {%0,%1,%2,%3};"
        : "+f"(d[0]), "+f"(d[1]), "+f"(d[2]), "+f"(d[3])
        : "r"(a[0]), "r"(a[1]), "r"(a[2]), "r"(a[3]), "r"(b0), "r"(b1));
}

// ===========================================================================
// Plain HGEMM (fp16 in, f32 acc), 128x64 tile, 2 CTAs/SM. Uniform per-CTA
// cost (twice validated: heterogeneous CTA mixes regress at this grid size).
//  PROJ=true:  C -> fp16 [row][1536] (+bias)
//  PROJ=false: C -> fp32 [row][N]
// ===========================================================================
constexpr int OFF_AH = 0;          // 128 rows x 64B
constexpr int OFF_BH = 8192;       // 32 rows x 128B
constexpr int STG = 12288;
constexpr int NSTAGE = 4;
constexpr int HG_SMEM = STG * NSTAGE;  // 49152

template <bool PROJ>
__global__ __launch_bounds__(256, 2) void hgemm_kernel(
    const __half* __restrict__ A, const __half* __restrict__ Bw,
    const float* __restrict__ bias, float* __restrict__ Cf,
    __half* __restrict__ Ch, int M, int N)
{
    extern __shared__ char smm[];
    uint32_t sb = smem_u32(smm);
    int tid = threadIdx.x, lane = tid & 31, wid = tid >> 5;
    int wm = wid >> 1, wn = wid & 1;
    int row0 = blockIdx.y * 128, col0 = blockIdx.x * 64;

    int idA0 = tid, idA1 = tid + 256;
    int rA0 = idA0 >> 2, cA0 = idA0 & 3;
    int rA1 = idA1 >> 2, cA1 = idA1 & 3;
    int gm0 = row0 + rA0, gm1 = row0 + rA1;
    int av0 = (gm0 < M) ? 16 : 0, av1 = (gm1 < M) ? 16 : 0;
    size_t arow0 = (gm0 < M) ? (size_t)gm0 : 0;
    size_t arow1 = (gm1 < M) ? (size_t)gm1 : 0;
    const __half* asrc0 = A + arow0 * 512 + cA0 * 8;
    const __half* asrc1 = A + arow1 * 512 + cA1 * 8;
    uint32_t adst0 = rA0 * 64 + (((cA0 + (rA0 >> 1)) & 3) << 4);
    uint32_t adst1 = rA1 * 64 + (((cA1 + (rA1 >> 1)) & 3) << 4);

    int rB = tid >> 3, cB = tid & 7;
    const __half* bsrc = Bw + (size_t)rB * N + col0 + cB * 8;
    uint32_t bdst = rB * 128 + ((cB ^ (rB & 7)) << 4);

    auto load_stage = [&](int s, int kt) {
        int k0 = kt * 32;
        uint32_t base = sb + s * STG;
        cpa16(base + OFF_AH + adst0, asrc0 + k0, av0);
        cpa16(base + OFF_AH + adst1, asrc1 + k0, av1);
        cpa16(base + OFF_BH + bdst, bsrc + (size_t)k0 * N, 16);
        cp_commit();
    };

    constexpr int KT = 512 / 32;   // 16
    load_stage(0, 0);
    load_stage(1, 1);
    load_stage(2, 2);

    float accf[2][4][4] = {};

    int la_r0 = wm * 32 + (lane & 15);
    int la_c0 = (lane >> 4);
    int lb_r0 = (lane & 15);
    int lb_c0 = wn * 4 + (lane >> 4);

    for (int kt = 0; kt < KT; kt++) {
        cp_wait<2>();
        __syncthreads();
        int s = kt & (NSTAGE - 1);
        uint32_t base = sb + s * STG;
#pragma unroll
        for (int kk = 0; kk < 2; kk++) {
            uint32_t ah[2][4];
#pragma unroll
            for (int mf = 0; mf < 2; mf++) {
                int r = la_r0 + mf * 16;
                int c = la_c0 + kk * 2;
                ldsm4(ah[mf], base + OFF_AH + r * 64 + (((c + (r >> 1)) & 3) << 4));
            }
            uint32_t bh[2][4];
#pragma unroll
            for (int nf = 0; nf < 2; nf++) {
                int r = lb_r0 + kk * 16;
                int c = lb_c0 + nf * 2;
                ldsm4t(bh[nf], base + OFF_BH + r * 128 + ((c ^ (r & 7)) << 4));
            }
#pragma unroll
            for (int mf = 0; mf < 2; mf++)
#pragma unroll
                for (int n = 0; n < 4; n++) {
                    int bi = n >> 1, br = (n & 1) * 2;
                    mma_f32(accf[mf][n], ah[mf], bh[bi][br], bh[bi][br + 1]);
                }
        }
        if (kt + 3 < KT) load_stage((kt + 3) & (NSTAGE - 1), kt + 3);
        else cp_commit();
    }

    // ---- epilogue ----
#pragma unroll
    for (int mf = 0; mf < 2; mf++) {
        int rb = row0 + wm * 32 + mf * 16 + (lane >> 2);
#pragma unroll
        for (int n = 0; n < 4; n++) {
            int cb = col0 + wn * 32 + n * 8 + (lane & 3) * 2;
            float* a4 = accf[mf][n];
            float bx = 0.f, by = 0.f;
            if (PROJ) { bx = bias[cb]; by = bias[cb + 1]; }
            float v00 = a4[0] + bx, v01 = a4[1] + by;
            float v10 = a4[2] + bx, v11 = a4[3] + by;
            if (PROJ) {
                if (rb < M)
                    *(__half2*)(Ch + (size_t)rb * 1536 + cb) = __floats2half2_rn(v00, v01);
                if (rb + 8 < M)
                    *(__half2*)(Ch + (size_t)(rb + 8) * 1536 + cb) = __floats2half2_rn(v10, v11);
            } else {
                if (rb < M)
                    *(float2*)(Cf + (size_t)rb * N + cb) = make_float2(v00, v01);
                if (rb + 8 < M)
                    *(float2*)(Cf + (size_t)(rb + 8) * N + cb) = make_float2(v10, v11);
            }
        }
    }
}

// ===========================================================================
// prep kernel: convX + convW2 + convWo + mask + hr(32 blocks) in one launch.
// Ranges: [0,2111) convX, [2111,2879) convW2, [2879,3135) convWo,
//         [3135,3261) mask, [3261,3293) hr (16 cols per block).
// ===========================================================================
constexpr int PREP_BLOCKS = 3293;

__global__ __launch_bounds__(256) void prep_kernel(
    const float* __restrict__ x, const float* __restrict__ r,
    const float* __restrict__ Wkv, const float* __restrict__ Wq,
    const float* __restrict__ bq, const float* __restrict__ Wr,
    const float* __restrict__ Wo)
{
    int bid = blockIdx.x, tid = threadIdx.x;
    if (bid < 2111) {
        int idx = bid * 256 + tid;
        int m = idx >> 7, k4 = (idx & 127) << 2;
        float4 v = *(const float4*)(x + (size_t)m * 512 + k4);
        __half* rb = g_xh + (size_t)m * 512;
        *(__half2*)(rb + k4) = __floats2half2_rn(v.x, v.y);
        *(__half2*)(rb + k4 + 2) = __floats2half2_rn(v.z, v.w);
    } else if (bid < 2879) {
        int idx = (bid - 2111) * 256 + tid;
        if (idx < 384) {
            float4 v = make_float4(0.f, 0.f, 0.f, 0.f);
            int n4 = idx * 4;
            if (n4 >= 1024) v = *(const float4*)(bq + n4 - 1024);
            *(float4*)(g_bias + n4) = v;
        }
        int k = idx / 384, n4 = (idx - k * 384) * 4;
        float4 v = (n4 < 1024) ? *(const float4*)(Wkv + (size_t)k * 1024 + n4)
                               : *(const float4*)(Wq + (size_t)k * 512 + n4 - 1024);
        __half* d0 = g_Wh + (size_t)k * 1536 + n4;
        *(__half2*)(d0) = __floats2half2_rn(v.x, v.y);
        *(__half2*)(d0 + 2) = __floats2half2_rn(v.z, v.w);
    } else if (bid < 3135) {
        int idx = (bid - 2879) * 256 + tid;
        int k = idx >> 7, n4 = (idx & 127) << 2;
        float4 v = *(const float4*)(Wo + (size_t)k * 512 + n4);
        __half* d0 = g_Woh + (size_t)k * 512 + n4;
        *(__half2*)(d0) = __floats2half2_rn(v.x, v.y);
        *(__half2*)(d0 + 2) = __floats2half2_rn(v.z, v.w);
    } else if (bid < 3261) {
        int mb = bid - 3135;
        int t = mb % (Cn - 1), b = mb / (Cn - 1);
        const float* row = x + ((size_t)b * Tn + t) * DMn;
        int zero = 1;
        for (int i = tid; i < DMn; i += 256)
            if (row[i] != 0.f) zero = 0;
        int all = __syncthreads_and(zero);
        if (tid == 0) g_mask[b * (Cn - 1) + t] = (unsigned char)(all != 0);
    } else {
        // hr: block cb computes hr[:, cb*16 : cb*16+16] = r @ Wr slice
        __shared__ float sa[64][33];
        __shared__ float sw[32][16];
        int cb = bid - 3261;
        int row = tid & 63, cg = tid >> 6;   // cg 0..3 -> 4 cols each
        float acc[4] = {};
        for (int k0 = 0; k0 < 512; k0 += 32) {
            for (int i = tid; i < 2048; i += 256) {
                int rr = i >> 5, kk = i & 31;
                sa[rr][kk] = r[rr * 512 + k0 + kk];
            }
            for (int i = tid; i < 512; i += 256) {
                int kk = i >> 4, cc = i & 15;
                sw[kk][cc] = Wr[(size_t)(k0 + kk) * 512 + cb * 16 + cc];
            }
            __syncthreads();
#pragma unroll 8
            for (int kk = 0; kk < 32; kk++) {
                float a = sa[row][kk];
#pragma unroll
                for (int c = 0; c < 4; c++)
                    acc[c] = fmaf(a, sw[kk][cg * 4 + c], acc[c]);
            }
            __syncthreads();
        }
        __half* dst = g_hrh + row * 512 + cb * 16 + cg * 4;
        *(__half2*)(dst) = __floats2half2_rn(acc[0], acc[1]);
        *(__half2*)(dst + 2) = __floats2half2_rn(acc[2], acc[3]);
    }
}

// ---------------------------------------------------------------------------
// Tensor-core attention, 3 CTAs/SM, plain fp16 V. Output: fp16.
// ---------------------------------------------------------------------------
constexpr int AS_V  = 0;
constexpr int AS_DYN = 9216;
constexpr int AS_TOTAL = AS_DYN + 17408;          // 26624 halves
constexpr int ATT_SMEM = AS_TOTAL * 2;            // 53248 B

__global__ __launch_bounds__(256, 3) void attn_kernel() {
    extern __shared__ __align__(16) __half sm[];
    __half* sV  = sm + AS_V;
    __half* sHq = sm + AS_DYN;
    __half* sKC = sm + AS_DYN + 4608;
    __half* sS  = sm + AS_DYN;            // overlays sHq/sKC after score MMA
    __half* sW  = sm + AS_DYN + 8320;

    int q0 = blockIdx.x * 64;
    int h = blockIdx.y, b = blockIdx.z;
    int tid = threadIdx.x, lane = tid & 31, wid = tid >> 5;
    int wm = wid >> 1, wn = wid & 1;

    const __half* pb = g_projh + (size_t)(b * Tn + q0) * 1536;

    for (int li = tid; li < 1024; li += 256) {
        int q = li >> 4, d4 = (li & 15) << 2;
        *(uint2*)(sHq + q * 72 + d4) =
            *(const uint2*)(pb + (size_t)(63 + q) * 1536 + 1024 + h * 64 + d4);
    }
    for (int li = tid; li < 2048; li += 256) {
        int j = li >> 4, d4 = (li & 15) << 2;
        __half hv[4];
        if (j < 127) *(uint2*)hv = *(const uint2*)(pb + (size_t)j * 1536 + h * 64 + d4);
        else { hv[0] = hv[1] = hv[2] = hv[3] = __half(0.f); }
        sKC[(d4 + 0) * 200 + j] = hv[0];
        sKC[(d4 + 1) * 200 + j] = hv[1];
        sKC[(d4 + 2) * 200 + j] = hv[2];
        sKC[(d4 + 3) * 200 + j] = hv[3];
    }
    for (int li = tid; li < 1024; li += 256) {
        int c = li >> 4, d4 = (li & 15) << 2;
        __half hv[4];
        *(uint2*)hv = *(const uint2*)(g_hrh + c * 512 + h * 64 + d4);
        sKC[(d4 + 0) * 200 + 128 + c] = hv[0];
        sKC[(d4 + 1) * 200 + 128 + c] = hv[1];
        sKC[(d4 + 2) * 200 + 128 + c] = hv[2];
        sKC[(d4 + 3) * 200 + 128 + c] = hv[3];
    }
    for (int li = tid; li < 2048; li += 256) {
        int j = li >> 4, d4 = (li & 15) << 2;
        uint2 hv = make_uint2(0, 0);
        if (j < 127) hv = *(const uint2*)(pb + (size_t)j * 1536 + 512 + h * 64 + d4);
        *(uint2*)(sV + j * 72 + d4) = hv;
    }
    __syncthreads();

    uint32_t uHq = smem_u32(sHq), uKC = smem_u32(sKC);
    float sacc[6][2][4] = {};
#pragma unroll
    for (int ks = 0; ks < 4; ks++) {
        uint32_t a[4];
        {
            int r = wm * 16 + (lane & 15);
            int c = (lane >> 4) + ks * 2;
            ldsm4(a, uHq + r * 144 + c * 16);
        }
#pragma unroll
        for (int nf = 0; nf < 6; nf++) {
            uint32_t bb[4];
            int r = (lane & 15) + ks * 16;
            int c = wn * 12 + nf * 2 + (lane >> 4);
            ldsm4t(bb, uKC + r * 400 + c * 16);
            mma_f32(sacc[nf][0], a, bb[0], bb[1]);
            mma_f32(sacc[nf][1], a, bb[2], bb[3]);
        }
    }
    __syncthreads();

    for (int i = tid; i < 64 * 136 / 2; i += 256) ((uint32_t*)sW)[i] = 0;
    {
        int row = wm * 16 + (lane >> 2);
        auto put = [&](int rr, int cc, float v) {
            int rel = cc - rr;
            if (rel >= 0 && rel < 64) sS[rr * 130 + rel] = __float2half_rn(v);
            else if (cc >= 128) sS[rr * 130 + 64 + (cc - 128)] = __float2half_rn(v);
        };
#pragma unroll
        for (int nf = 0; nf < 6; nf++)
#pragma unroll
            for (int sub = 0; sub < 2; sub++) {
                int col = wn * 96 + nf * 16 + sub * 8 + (lane & 3) * 2;
                float* c4 = sacc[nf][sub];
                put(row, col, c4[0]);     put(row, col + 1, c4[1]);
                put(row + 8, col, c4[2]); put(row + 8, col + 1, c4[3]);
            }
    }
    __syncthreads();

    {
        int w = tid >> 5;
#pragma unroll
        for (int rr = 0; rr < 8; rr++) {
            int q = w * 8 + rr;
            int c0 = lane, c1 = lane + 32;
            float s0 = (__half2float(sS[q * 130 + c0]) +
                        __half2float(sS[q * 130 + 64 + c0])) * 0.125f;
            float s1 = (__half2float(sS[q * 130 + c1]) +
                        __half2float(sS[q * 130 + 64 + c1])) * 0.125f;
            int jg0 = q0 + q + c0, jg1 = q0 + q + c1;
            if (jg0 < Cn - 1 && g_mask[b * (Cn - 1) + jg0]) s0 = -1e30f;
            if (jg1 < Cn - 1 && g_mask[b * (Cn - 1) + jg1]) s1 = -1e30f;
            float mx = fmaxf(s0, s1);
#pragma unroll
            for (int o = 16; o; o >>= 1) mx = fmaxf(mx, __shfl_xor_sync(0xffffffffu, mx, o));
            float e0 = __expf(s0 - mx), e1 = __expf(s1 - mx);
            float sum = e0 + e1;
#pragma unroll
            for (int o = 16; o; o >>= 1) sum += __shfl_xor_sync(0xffffffffu, sum, o);
            float inv = 1.f / sum;
            sW[q * 136 + q + c0] = __float2half_rn(e0 * inv);
            sW[q * 136 + q + c1] = __float2half_rn(e1 * inv);
        }
    }
    __syncthreads();

    uint32_t uW = smem_u32(sW), uV = smem_u32(sV);
    {
        float ohi[4][4] = {};
#pragma unroll
        for (int ks = 0; ks < 8; ks++) {
            uint32_t a[4];
            {
                int r = wm * 16 + (lane & 15);
                int c = (lane >> 4) + ks * 2;
                ldsm4(a, uW + r * 272 + c * 16);
            }
#pragma unroll
            for (int nf = 0; nf < 2; nf++) {
                uint32_t bh[4];
                int r = (lane & 15) + ks * 16;
                int c = wn * 4 + nf * 2 + (lane >> 4);
                ldsm4t(bh, uV + r * 144 + c * 16);
                mma_f32(ohi[nf * 2], a, bh[0], bh[1]);
                mma_f32(ohi[nf * 2 + 1], a, bh[2], bh[3]);
            }
        }
        int row = wm * 16 + (lane >> 2);
#pragma unroll
        for (int n = 0; n < 4; n++) {
            int col = wn * 32 + n * 8 + (lane & 3) * 2;
#pragma unroll
            for (int rr = 0; rr < 2; rr++) {
                float ox = ohi[n][rr * 2], oy = ohi[n][rr * 2 + 1];
                int q = row + rr * 8;
                __half* dst = g_atth + (size_t)(b * Qn + q0 + q) * 512 + h * 64 + col;
                *(__half2*)(dst) = __floats2half2_rn(ox, oy);
            }
        }
    }
}

}  // namespace

// ---------------------------------------------------------------------------
extern "C" void kernel_launch(void* const* d_in, const int* in_sizes, int n_in,
                              void* d_out, int out_size) {
    const float* x   = (const float*)d_in[0];
    const float* r   = (const float*)d_in[1];
    const float* Wkv = (const float*)d_in[2];
    const float* Wq  = (const float*)d_in[3];
    const float* bq  = (const float*)d_in[4];
    const float* Wr  = (const float*)d_in[5];
    const float* Wo  = (const float*)d_in[6];
    float* out = (float*)d_out;

    float* biasp;
    __half *xh, *atth, *Wh, *Woh, *projh;
    cudaGetSymbolAddress((void**)&biasp, g_bias);
    cudaGetSymbolAddress((void**)&xh,    g_xh);
    cudaGetSymbolAddress((void**)&atth,  g_atth);
    cudaGetSymbolAddress((void**)&Wh,    g_Wh);
    cudaGetSymbolAddress((void**)&Woh,   g_Woh);
    cudaGetSymbolAddress((void**)&projh, g_projh);

    cudaFuncSetAttribute(attn_kernel, cudaFuncAttributeMaxDynamicSharedMemorySize, ATT_SMEM);
    cudaFuncSetAttribute(hgemm_kernel<true>,
                         cudaFuncAttributeMaxDynamicSharedMemorySize, HG_SMEM);
    cudaFuncSetAttribute(hgemm_kernel<false>,
                         cudaFuncAttributeMaxDynamicSharedMemorySize, HG_SMEM);

    // 1: prep (convX + convW2 + convWo + mask + hr)
    prep_kernel<<<PREP_BLOCKS, 256>>>(x, r, Wkv, Wq, bq, Wr, Wo);
    // 2: proj = x @ [Wkv|Wq] + [0|bq] -> fp16 (uniform f32acc)
    hgemm_kernel<true><<<dim3(24, 33), 256, HG_SMEM>>>(
        xh, Wh, biasp, nullptr, projh, Bn * Tn, 1536);
    // 3: tensor-core attention -> fp16 att
    attn_kernel<<<dim3(Qn / 64, Hn, Bn), 256, ATT_SMEM>>>();
    // 4: out = att @ Wo  (f32 acc, fp32 output)
    hgemm_kernel<false><<<dim3(8, 32), 256, HG_SMEM>>>(
        atth, Woh, nullptr, out, nullptr, Bn * Qn, 512);
}

// round 17
// speedup vs baseline: 1.1209x; 1.0461x over previous
#include <cuda_runtime.h>
#include <cuda_fp16.h>
#include <cstdint>

namespace {

constexpr int Bn = 2, Tn = 2111, Qn = 2048, Cn = 64, Hn = 8, DMn = 512;

// Scratch (device globals) — plain fp16 pipeline
__device__ __half g_projh[(size_t)Bn * Tn * 1536];  // [k|v|hq] fp16
__device__ __half g_hrh[Cn * 512];
__device__ float g_bias[1536];
__device__ unsigned char g_mask[Bn * (Cn - 1)];
__device__ __half g_xh[(size_t)Bn * Tn * 512];
__device__ __half g_atth[(size_t)Bn * Qn * 512];
__device__ __half g_Wh[512 * 1536];                 // [Wkv | Wq]
__device__ __half g_Woh[512 * 512];                 // Wo

// ===========================================================================
// PTX helpers
// ===========================================================================
__device__ __forceinline__ uint32_t smem_u32(const void* p) {
    uint32_t a;
    asm("{ .reg .u64 t; cvta.to.shared.u64 t, %1; cvt.u32.u64 %0, t; }" : "=r"(a) : "l"(p));
    return a;
}
__device__ __forceinline__ void cpa16(uint32_t d, const void* s, int sz) {
    asm volatile("cp.async.cg.shared.global [%0], [%1], 16, %2;" :: "r"(d), "l"(s), "r"(sz));
}
__device__ __forceinline__ void cp_commit() { asm volatile("cp.async.commit_group;"); }
template <int N> __device__ __forceinline__ void cp_wait() {
    asm volatile("cp.async.wait_group %0;" :: "n"(N));
}
__device__ __forceinline__ void ldsm4(uint32_t* r, uint32_t a) {
    asm volatile("ldmatrix.sync.aligned.m8n8.x4.shared.b16 {%0,%1,%2,%3}, [%4];"
                 : "=r"(r[0]), "=r"(r[1]), "=r"(r[2]), "=r"(r[3]) : "r"(a));
}
__device__ __forceinline__ void ldsm4t(uint32_t* r, uint32_t a) {
    asm volatile("ldmatrix.sync.aligned.m8n8.x4.trans.shared.b16 {%0,%1,%2,%3}, [%4];"
                 : "=r"(r[0]), "=r"(r[1]), "=r"(r[2]), "=r"(r[3]) : "r"(a));
}
__device__ __forceinline__ void mma_f32(float* d, const uint32_t* a, uint32_t b0, uint32_t b1) {
    asm volatile(
        "mma.sync.aligned.m16n8k16.row.col.f32.f16.f16.f32 "
        "{%0,%1,%2,%3}, {%4,%5,%6,%7}, {%8,%9}, {%0,%1,%2,%3};"
        : "+f"(d[0]), "+f"(d[1]), "+f"(d[2]), "+f"(d[3])
        : "r"(a[0]), "r"(a[1]), "r"(a[2]), "r"(a[3]), "r"(b0), "r"(b1));
}
__device__ __forceinline__ void grid_dep_sync() {
#if __CUDA_ARCH__ >= 900
    asm volatile("griddepcontrol.wait;" ::: "memory");
#endif
}

// ===========================================================================
// Plain HGEMM (fp16 in, f32 acc), 128x64 tile, 2 CTAs/SM.
//  PROJ=true:  C -> fp16 [row][1536] (+bias)
//  PROJ=false: C -> fp32 [row][N]
// Both are PDL consumers: grid_dep_sync before first dependent load.
// ===========================================================================
constexpr int OFF_AH = 0;
constexpr int OFF_BH = 8192;
constexpr int STG = 12288;
constexpr int NSTAGE = 4;
constexpr int HG_SMEM = STG * NSTAGE;  // 49152

template <bool PROJ>
__global__ __launch_bounds__(256, 2) void hgemm_kernel(
    const __half* __restrict__ A, const __half* __restrict__ Bw,
    const float* __restrict__ bias, float* __restrict__ Cf,
    __half* __restrict__ Ch, int M, int N)
{
    extern __shared__ char smm[];
    uint32_t sb = smem_u32(smm);
    int tid = threadIdx.x, lane = tid & 31, wid = tid >> 5;
    int wm = wid >> 1, wn = wid & 1;
    int row0 = blockIdx.y * 128, col0 = blockIdx.x * 64;

    int idA0 = tid, idA1 = tid + 256;
    int rA0 = idA0 >> 2, cA0 = idA0 & 3;
    int rA1 = idA1 >> 2, cA1 = idA1 & 3;
    int gm0 = row0 + rA0, gm1 = row0 + rA1;
    int av0 = (gm0 < M) ? 16 : 0, av1 = (gm1 < M) ? 16 : 0;
    size_t arow0 = (gm0 < M) ? (size_t)gm0 : 0;
    size_t arow1 = (gm1 < M) ? (size_t)gm1 : 0;
    const __half* asrc0 = A + arow0 * 512 + cA0 * 8;
    const __half* asrc1 = A + arow1 * 512 + cA1 * 8;
    uint32_t adst0 = rA0 * 64 + (((cA0 + (rA0 >> 1)) & 3) << 4);
    uint32_t adst1 = rA1 * 64 + (((cA1 + (rA1 >> 1)) & 3) << 4);

    int rB = tid >> 3, cB = tid & 7;
    const __half* bsrc = Bw + (size_t)rB * N + col0 + cB * 8;
    uint32_t bdst = rB * 128 + ((cB ^ (rB & 7)) << 4);

    auto load_stage = [&](int s, int kt) {
        int k0 = kt * 32;
        uint32_t base = sb + s * STG;
        cpa16(base + OFF_AH + adst0, asrc0 + k0, av0);
        cpa16(base + OFF_AH + adst1, asrc1 + k0, av1);
        cpa16(base + OFF_BH + bdst, bsrc + (size_t)k0 * N, 16);
        cp_commit();
    };

    grid_dep_sync();   // PDL: wait for producer's memory before first load

    constexpr int KT = 512 / 32;   // 16
    load_stage(0, 0);
    load_stage(1, 1);
    load_stage(2, 2);

    float accf[2][4][4] = {};

    int la_r0 = wm * 32 + (lane & 15);
    int la_c0 = (lane >> 4);
    int lb_r0 = (lane & 15);
    int lb_c0 = wn * 4 + (lane >> 4);

    for (int kt = 0; kt < KT; kt++) {
        cp_wait<2>();
        __syncthreads();
        int s = kt & (NSTAGE - 1);
        uint32_t base = sb + s * STG;
#pragma unroll
        for (int kk = 0; kk < 2; kk++) {
            uint32_t ah[2][4];
#pragma unroll
            for (int mf = 0; mf < 2; mf++) {
                int r = la_r0 + mf * 16;
                int c = la_c0 + kk * 2;
                ldsm4(ah[mf], base + OFF_AH + r * 64 + (((c + (r >> 1)) & 3) << 4));
            }
            uint32_t bh[2][4];
#pragma unroll
            for (int nf = 0; nf < 2; nf++) {
                int r = lb_r0 + kk * 16;
                int c = lb_c0 + nf * 2;
                ldsm4t(bh[nf], base + OFF_BH + r * 128 + ((c ^ (r & 7)) << 4));
            }
#pragma unroll
            for (int mf = 0; mf < 2; mf++)
#pragma unroll
                for (int n = 0; n < 4; n++) {
                    int bi = n >> 1, br = (n & 1) * 2;
                    mma_f32(accf[mf][n], ah[mf], bh[bi][br], bh[bi][br + 1]);
                }
        }
        if (kt + 3 < KT) load_stage((kt + 3) & (NSTAGE - 1), kt + 3);
        else cp_commit();
    }

#pragma unroll
    for (int mf = 0; mf < 2; mf++) {
        int rb = row0 + wm * 32 + mf * 16 + (lane >> 2);
#pragma unroll
        for (int n = 0; n < 4; n++) {
            int cb = col0 + wn * 32 + n * 8 + (lane & 3) * 2;
            float* a4 = accf[mf][n];
            float bx = 0.f, by = 0.f;
            if (PROJ) { bx = bias[cb]; by = bias[cb + 1]; }
            float v00 = a4[0] + bx, v01 = a4[1] + by;
            float v10 = a4[2] + bx, v11 = a4[3] + by;
            if (PROJ) {
                if (rb < M)
                    *(__half2*)(Ch + (size_t)rb * 1536 + cb) = __floats2half2_rn(v00, v01);
                if (rb + 8 < M)
                    *(__half2*)(Ch + (size_t)(rb + 8) * 1536 + cb) = __floats2half2_rn(v10, v11);
            } else {
                if (rb < M)
                    *(float2*)(Cf + (size_t)rb * N + cb) = make_float2(v00, v01);
                if (rb + 8 < M)
                    *(float2*)(Cf + (size_t)(rb + 8) * N + cb) = make_float2(v10, v11);
            }
        }
    }
}

// ===========================================================================
// prep kernel: convX + convW2 + convWo + mask + hr(32 blocks) in one launch.
// ===========================================================================
constexpr int PREP_BLOCKS = 3293;

__global__ __launch_bounds__(256) void prep_kernel(
    const float* __restrict__ x, const float* __restrict__ r,
    const float* __restrict__ Wkv, const float* __restrict__ Wq,
    const float* __restrict__ bq, const float* __restrict__ Wr,
    const float* __restrict__ Wo)
{
    int bid = blockIdx.x, tid = threadIdx.x;
    if (bid < 2111) {
        int idx = bid * 256 + tid;
        int m = idx >> 7, k4 = (idx & 127) << 2;
        float4 v = *(const float4*)(x + (size_t)m * 512 + k4);
        __half* rb = g_xh + (size_t)m * 512;
        *(__half2*)(rb + k4) = __floats2half2_rn(v.x, v.y);
        *(__half2*)(rb + k4 + 2) = __floats2half2_rn(v.z, v.w);
    } else if (bid < 2879) {
        int idx = (bid - 2111) * 256 + tid;
        if (idx < 384) {
            float4 v = make_float4(0.f, 0.f, 0.f, 0.f);
            int n4 = idx * 4;
            if (n4 >= 1024) v = *(const float4*)(bq + n4 - 1024);
            *(float4*)(g_bias + n4) = v;
        }
        int k = idx / 384, n4 = (idx - k * 384) * 4;
        float4 v = (n4 < 1024) ? *(const float4*)(Wkv + (size_t)k * 1024 + n4)
                               : *(const float4*)(Wq + (size_t)k * 512 + n4 - 1024);
        __half* d0 = g_Wh + (size_t)k * 1536 + n4;
        *(__half2*)(d0) = __floats2half2_rn(v.x, v.y);
        *(__half2*)(d0 + 2) = __floats2half2_rn(v.z, v.w);
    } else if (bid < 3135) {
        int idx = (bid - 2879) * 256 + tid;
        int k = idx >> 7, n4 = (idx & 127) << 2;
        float4 v = *(const float4*)(Wo + (size_t)k * 512 + n4);
        __half* d0 = g_Woh + (size_t)k * 512 + n4;
        *(__half2*)(d0) = __floats2half2_rn(v.x, v.y);
        *(__half2*)(d0 + 2) = __floats2half2_rn(v.z, v.w);
    } else if (bid < 3261) {
        int mb = bid - 3135;
        int t = mb % (Cn - 1), b = mb / (Cn - 1);
        const float* row = x + ((size_t)b * Tn + t) * DMn;
        int zero = 1;
        for (int i = tid; i < DMn; i += 256)
            if (row[i] != 0.f) zero = 0;
        int all = __syncthreads_and(zero);
        if (tid == 0) g_mask[b * (Cn - 1) + t] = (unsigned char)(all != 0);
    } else {
        __shared__ float sa[64][33];
        __shared__ float sw[32][16];
        int cb = bid - 3261;
        int row = tid & 63, cg = tid >> 6;
        float acc[4] = {};
        for (int k0 = 0; k0 < 512; k0 += 32) {
            for (int i = tid; i < 2048; i += 256) {
                int rr = i >> 5, kk = i & 31;
                sa[rr][kk] = r[rr * 512 + k0 + kk];
            }
            for (int i = tid; i < 512; i += 256) {
                int kk = i >> 4, cc = i & 15;
                sw[kk][cc] = Wr[(size_t)(k0 + kk) * 512 + cb * 16 + cc];
            }
            __syncthreads();
#pragma unroll 8
            for (int kk = 0; kk < 32; kk++) {
                float a = sa[row][kk];
#pragma unroll
                for (int c = 0; c < 4; c++)
                    acc[c] = fmaf(a, sw[kk][cg * 4 + c], acc[c]);
            }
            __syncthreads();
        }
        __half* dst = g_hrh + row * 512 + cb * 16 + cg * 4;
        *(__half2*)(dst) = __floats2half2_rn(acc[0], acc[1]);
        *(__half2*)(dst + 2) = __floats2half2_rn(acc[2], acc[3]);
    }
}

// ---------------------------------------------------------------------------
// Tensor-core attention, 3 CTAs/SM, plain fp16 V. Output: fp16. PDL consumer.
// Out-MMA: band-exact K skip — warp wm needs only ks in [wm, wm+4].
// ---------------------------------------------------------------------------
constexpr int AS_V  = 0;
constexpr int AS_DYN = 9216;
constexpr int AS_TOTAL = AS_DYN + 17408;
constexpr int ATT_SMEM = AS_TOTAL * 2;            // 53248 B

__global__ __launch_bounds__(256, 3) void attn_kernel() {
    extern __shared__ __align__(16) __half sm[];
    __half* sV  = sm + AS_V;
    __half* sHq = sm + AS_DYN;
    __half* sKC = sm + AS_DYN + 4608;
    __half* sS  = sm + AS_DYN;
    __half* sW  = sm + AS_DYN + 8320;

    int q0 = blockIdx.x * 64;
    int h = blockIdx.y, b = blockIdx.z;
    int tid = threadIdx.x, lane = tid & 31, wid = tid >> 5;
    int wm = wid >> 1, wn = wid & 1;

    const __half* pb = g_projh + (size_t)(b * Tn + q0) * 1536;

    grid_dep_sync();   // PDL: proj results must be visible

    for (int li = tid; li < 1024; li += 256) {
        int q = li >> 4, d4 = (li & 15) << 2;
        *(uint2*)(sHq + q * 72 + d4) =
            *(const uint2*)(pb + (size_t)(63 + q) * 1536 + 1024 + h * 64 + d4);
    }
    for (int li = tid; li < 2048; li += 256) {
        int j = li >> 4, d4 = (li & 15) << 2;
        __half hv[4];
        if (j < 127) *(uint2*)hv = *(const uint2*)(pb + (size_t)j * 1536 + h * 64 + d4);
        else { hv[0] = hv[1] = hv[2] = hv[3] = __half(0.f); }
        sKC[(d4 + 0) * 200 + j] = hv[0];
        sKC[(d4 + 1) * 200 + j] = hv[1];
        sKC[(d4 + 2) * 200 + j] = hv[2];
        sKC[(d4 + 3) * 200 + j] = hv[3];
    }
    for (int li = tid; li < 1024; li += 256) {
        int c = li >> 4, d4 = (li & 15) << 2;
        __half hv[4];
        *(uint2*)hv = *(const uint2*)(g_hrh + c * 512 + h * 64 + d4);
        sKC[(d4 + 0) * 200 + 128 + c] = hv[0];
        sKC[(d4 + 1) * 200 + 128 + c] = hv[1];
        sKC[(d4 + 2) * 200 + 128 + c] = hv[2];
        sKC[(d4 + 3) * 200 + 128 + c] = hv[3];
    }
    for (int li = tid; li < 2048; li += 256) {
        int j = li >> 4, d4 = (li & 15) << 2;
        uint2 hv = make_uint2(0, 0);
        if (j < 127) hv = *(const uint2*)(pb + (size_t)j * 1536 + 512 + h * 64 + d4);
        *(uint2*)(sV + j * 72 + d4) = hv;
    }
    __syncthreads();

    uint32_t uHq = smem_u32(sHq), uKC = smem_u32(sKC);
    float sacc[6][2][4] = {};
#pragma unroll
    for (int ks = 0; ks < 4; ks++) {
        uint32_t a[4];
        {
            int r = wm * 16 + (lane & 15);
            int c = (lane >> 4) + ks * 2;
            ldsm4(a, uHq + r * 144 + c * 16);
        }
#pragma unroll
        for (int nf = 0; nf < 6; nf++) {
            uint32_t bb[4];
            int r = (lane & 15) + ks * 16;
            int c = wn * 12 + nf * 2 + (lane >> 4);
            ldsm4t(bb, uKC + r * 400 + c * 16);
            mma_f32(sacc[nf][0], a, bb[0], bb[1]);
            mma_f32(sacc[nf][1], a, bb[2], bb[3]);
        }
    }
    __syncthreads();

    for (int i = tid; i < 64 * 136 / 2; i += 256) ((uint32_t*)sW)[i] = 0;
    {
        int row = wm * 16 + (lane >> 2);
        auto put = [&](int rr, int cc, float v) {
            int rel = cc - rr;
            if (rel >= 0 && rel < 64) sS[rr * 130 + rel] = __float2half_rn(v);
            else if (cc >= 128) sS[rr * 130 + 64 + (cc - 128)] = __float2half_rn(v);
        };
#pragma unroll
        for (int nf = 0; nf < 6; nf++)
#pragma unroll
            for (int sub = 0; sub < 2; sub++) {
                int col = wn * 96 + nf * 16 + sub * 8 + (lane & 3) * 2;
                float* c4 = sacc[nf][sub];
                put(row, col, c4[0]);     put(row, col + 1, c4[1]);
                put(row + 8, col, c4[2]); put(row + 8, col + 1, c4[3]);
            }
    }
    __syncthreads();

    {
        int w = tid >> 5;
#pragma unroll
        for (int rr = 0; rr < 8; rr++) {
            int q = w * 8 + rr;
            int c0 = lane, c1 = lane + 32;
            float s0 = (__half2float(sS[q * 130 + c0]) +
                        __half2float(sS[q * 130 + 64 + c0])) * 0.125f;
            float s1 = (__half2float(sS[q * 130 + c1]) +
                        __half2float(sS[q * 130 + 64 + c1])) * 0.125f;
            int jg0 = q0 + q + c0, jg1 = q0 + q + c1;
            if (jg0 < Cn - 1 && g_mask[b * (Cn - 1) + jg0]) s0 = -1e30f;
            if (jg1 < Cn - 1 && g_mask[b * (Cn - 1) + jg1]) s1 = -1e30f;
            float mx = fmaxf(s0, s1);
#pragma unroll
            for (int o = 16; o; o >>= 1) mx = fmaxf(mx, __shfl_xor_sync(0xffffffffu, mx, o));
            float e0 = __expf(s0 - mx), e1 = __expf(s1 - mx);
            float sum = e0 + e1;
#pragma unroll
            for (int o = 16; o; o >>= 1) sum += __shfl_xor_sync(0xffffffffu, sum, o);
            float inv = 1.f / sum;
            sW[q * 136 + q + c0] = __float2half_rn(e0 * inv);
            sW[q * 136 + q + c1] = __float2half_rn(e1 * inv);
        }
    }
    __syncthreads();

    uint32_t uW = smem_u32(sW), uV = smem_u32(sV);
    {
        float ohi[4][4] = {};
        // band-exact: rows [wm*16, wm*16+15] have nonzero W only for
        // j in [wm*16, wm*16+78] -> ks in [wm, wm+4]. Skipped terms are +0.
#pragma unroll
        for (int kss = 0; kss < 5; kss++) {
            int ks = wm + kss;
            uint32_t a[4];
            {
                int r = wm * 16 + (lane & 15);
                int c = (lane >> 4) + ks * 2;
                ldsm4(a, uW + r * 272 + c * 16);
            }
#pragma unroll
            for (int nf = 0; nf < 2; nf++) {
                uint32_t bh[4];
                int r = (lane & 15) + ks * 16;
                int c = wn * 4 + nf * 2 + (lane >> 4);
                ldsm4t(bh, uV + r * 144 + c * 16);
                mma_f32(ohi[nf * 2], a, bh[0], bh[1]);
                mma_f32(ohi[nf * 2 + 1], a, bh[2], bh[3]);
            }
        }
        int row = wm * 16 + (lane >> 2);
#pragma unroll
        for (int n = 0; n < 4; n++) {
            int col = wn * 32 + n * 8 + (lane & 3) * 2;
#pragma unroll
            for (int rr = 0; rr < 2; rr++) {
                float ox = ohi[n][rr * 2], oy = ohi[n][rr * 2 + 1];
                int q = row + rr * 8;
                __half* dst = g_atth + (size_t)(b * Qn + q0 + q) * 512 + h * 64 + col;
                *(__half2*)(dst) = __floats2half2_rn(ox, oy);
            }
        }
    }
}

}  // namespace

// ---------------------------------------------------------------------------
extern "C" void kernel_launch(void* const* d_in, const int* in_sizes, int n_in,
                              void* d_out, int out_size) {
    const float* x   = (const float*)d_in[0];
    const float* r   = (const float*)d_in[1];
    const float* Wkv = (const float*)d_in[2];
    const float* Wq  = (const float*)d_in[3];
    const float* bq  = (const float*)d_in[4];
    const float* Wr  = (const float*)d_in[5];
    const float* Wo  = (const float*)d_in[6];
    float* out = (float*)d_out;

    float* biasp;
    __half *xh, *atth, *Wh, *Woh, *projh;
    cudaGetSymbolAddress((void**)&biasp, g_bias);
    cudaGetSymbolAddress((void**)&xh,    g_xh);
    cudaGetSymbolAddress((void**)&atth,  g_atth);
    cudaGetSymbolAddress((void**)&Wh,    g_Wh);
    cudaGetSymbolAddress((void**)&Woh,   g_Woh);
    cudaGetSymbolAddress((void**)&projh, g_projh);

    cudaFuncSetAttribute(attn_kernel, cudaFuncAttributeMaxDynamicSharedMemorySize, ATT_SMEM);
    cudaFuncSetAttribute(hgemm_kernel<true>,
                         cudaFuncAttributeMaxDynamicSharedMemorySize, HG_SMEM);
    cudaFuncSetAttribute(hgemm_kernel<false>,
                         cudaFuncAttributeMaxDynamicSharedMemorySize, HG_SMEM);

    // PDL attribute for dependent launches
    cudaLaunchAttribute pdl[1];
    pdl[0].id = cudaLaunchAttributeProgrammaticStreamSerialization;
    pdl[0].val.programmaticStreamSerializationAllowed = 1;

    // 1: prep (plain launch)
    prep_kernel<<<PREP_BLOCKS, 256>>>(x, r, Wkv, Wq, bq, Wr, Wo);

    // 2: proj (PDL consumer of prep)
    {
        cudaLaunchConfig_t cfg = {};
        cfg.gridDim = dim3(24, 33);
        cfg.blockDim = dim3(256);
        cfg.dynamicSmemBytes = HG_SMEM;
        cfg.attrs = pdl; cfg.numAttrs = 1;
        cudaLaunchKernelEx(&cfg, hgemm_kernel<true>,
                           (const __half*)xh, (const __half*)Wh, (const float*)biasp,
                           (float*)nullptr, projh, Bn * Tn, 1536);
    }
    // 3: attention (PDL consumer of proj)
    {
        cudaLaunchConfig_t cfg = {};
        cfg.gridDim = dim3(Qn / 64, Hn, Bn);
        cfg.blockDim = dim3(256);
        cfg.dynamicSmemBytes = ATT_SMEM;
        cfg.attrs = pdl; cfg.numAttrs = 1;
        cudaLaunchKernelEx(&cfg, attn_kernel);
    }
    // 4: Wo (PDL consumer of attention)
    {
        cudaLaunchConfig_t cfg = {};
        cfg.gridDim = dim3(8, 32);
        cfg.blockDim = dim3(256);
        cfg.dynamicSmemBytes = HG_SMEM;
        cfg.attrs = pdl; cfg.numAttrs = 1;
        cudaLaunchKernelEx(&cfg, hgemm_kernel<false>,
                           (const __half*)atth, (const __half*)Woh, (const float*)nullptr,
                           out, (__half*)nullptr, Bn * Qn, 512);
    }
}